// round 1
// baseline (speedup 1.0000x reference)
#include <cuda_runtime.h>

// Problem constants
#define M_TOK  8192      // B*T
#define DMODEL 1024
#define TSEQ   1024
#define NHEADS 16
#define HDIM   64

// Scratch (device globals: allocation-free rule)
__device__ float g_q [M_TOK * DMODEL];
__device__ float g_k [M_TOK * DMODEL];
__device__ float g_v [M_TOK * DMODEL];
__device__ float g_ao[M_TOK * DMODEL];

// ---------------------------------------------------------------------------
// GEMM  C = A @ W^T   (A: [M,1024] row-major, W: [1024,1024] row-major)
// Both operands are K-contiguous ("NT" gemm). 128x128x8 tiling, 8x8/thread.
// QKV=true : A = x param, z in {0,1,2} selects (Wk->g_k, Wq->g_q, Wv->g_v)
// QKV=false: A = g_ao, W = W0, C = Cout (the harness output)
// ---------------------------------------------------------------------------
template <bool QKV>
__global__ __launch_bounds__(256)
void gemm_nt(const float* __restrict__ A,
             const float* __restrict__ W0,
             const float* __restrict__ W1,
             const float* __restrict__ W2,
             float* __restrict__ Cout)
{
    const float* W;
    float* C;
    if (QKV) {
        const int z = blockIdx.z;
        W = (z == 0) ? W0 : (z == 1) ? W1 : W2;
        C = (z == 0) ? g_k : (z == 1) ? g_q : g_v;
    } else {
        W = W0;
        C = Cout;
    }
    const float* Asrc = QKV ? A : (const float*)g_ao;

    __shared__ float As[8][128];
    __shared__ float Bs[8][128];

    const int tid  = threadIdx.x;
    const int m0   = blockIdx.x * 128;
    const int n0   = blockIdx.y * 128;
    const int lrow = tid >> 1;          // 0..127
    const int lk   = (tid & 1) * 4;     // 0 or 4
    const float* Ap = Asrc + (size_t)(m0 + lrow) * DMODEL + lk;
    const float* Wp = W    + (size_t)(n0 + lrow) * DMODEL + lk;

    const int tm = (tid >> 4) * 8;      // 0..120
    const int tn = (tid & 15) * 8;      // 0..120

    float acc[8][8];
#pragma unroll
    for (int i = 0; i < 8; i++)
#pragma unroll
        for (int j = 0; j < 8; j++) acc[i][j] = 0.0f;

    for (int kt = 0; kt < DMODEL; kt += 8) {
        const float4 av = *(const float4*)(Ap + kt);
        const float4 wv = *(const float4*)(Wp + kt);
        __syncthreads();   // protect smem from previous iteration's readers
        As[lk + 0][lrow] = av.x; As[lk + 1][lrow] = av.y;
        As[lk + 2][lrow] = av.z; As[lk + 3][lrow] = av.w;
        Bs[lk + 0][lrow] = wv.x; Bs[lk + 1][lrow] = wv.y;
        Bs[lk + 2][lrow] = wv.z; Bs[lk + 3][lrow] = wv.w;
        __syncthreads();
#pragma unroll
        for (int kk = 0; kk < 8; kk++) {
            const float4 a0 = *(const float4*)&As[kk][tm];
            const float4 a1 = *(const float4*)&As[kk][tm + 4];
            const float4 b0 = *(const float4*)&Bs[kk][tn];
            const float4 b1 = *(const float4*)&Bs[kk][tn + 4];
            const float a[8] = {a0.x, a0.y, a0.z, a0.w, a1.x, a1.y, a1.z, a1.w};
            const float b[8] = {b0.x, b0.y, b0.z, b0.w, b1.x, b1.y, b1.z, b1.w};
#pragma unroll
            for (int i = 0; i < 8; i++)
#pragma unroll
                for (int j = 0; j < 8; j++) acc[i][j] += a[i] * b[j];
        }
    }

#pragma unroll
    for (int i = 0; i < 8; i++) {
        float4 o0 = make_float4(acc[i][0], acc[i][1], acc[i][2], acc[i][3]);
        float4 o1 = make_float4(acc[i][4], acc[i][5], acc[i][6], acc[i][7]);
        float* cp = C + (size_t)(m0 + tm + i) * DMODEL + n0 + tn;
        *(float4*)(cp)     = o0;
        *(float4*)(cp + 4) = o1;
    }
}

// ---------------------------------------------------------------------------
// Flash attention (causal, fp32, online softmax).
// Block = (q-tile of 64 rows) x (one b,h pair). 256 threads = 16x16,
// each thread owns a 4x4 tile of S / O. Head dim = 64. scale = 1/8.
// SMEM: Qs/Ks transposed [k][row] (stride 68), Vs [c][oc], Ps [row][c].
// ---------------------------------------------------------------------------
#define FL_STR 68
#define FL_SMEM_FLOATS (4 * 64 * FL_STR)

__global__ __launch_bounds__(256)
void flash_attn()
{
    extern __shared__ float sm[];
    float* Qs = sm;                    // [64][68]  (Qs[kk][row])
    float* Ks = sm + 64 * FL_STR;      // [64][68]  (Ks[kk][col])
    float* Vs = sm + 2 * 64 * FL_STR;  // [64][68]  (Vs[c][oc])
    float* Ps = sm + 3 * 64 * FL_STR;  // [64][68]  (Ps[row][c])

    const int qt = blockIdx.x;          // 0..15
    const int b  = blockIdx.y >> 4;
    const int h  = blockIdx.y & 15;
    const size_t base = (size_t)b * TSEQ * DMODEL + (size_t)h * HDIM;
    const float* Qg = g_q + base;
    const float* Kg = g_k + base;
    const float* Vg = g_v + base;
    float*       Og = g_ao + base;

    const int tid = threadIdx.x;
    const int ty  = tid >> 4;           // 0..15 -> rows ty*4..ty*4+3
    const int tx  = tid & 15;           // 0..15 -> cols tx*4..tx*4+3

    // Load Q tile transposed: Qs[kk][r] = Q[qt*64+r][kk]
    for (int i = tid; i < 64 * 16; i += 256) {
        const int r  = i >> 4;
        const int k0 = (i & 15) << 2;
        const float4 v = *(const float4*)(Qg + (size_t)(qt * 64 + r) * DMODEL + k0);
        Qs[(k0 + 0) * FL_STR + r] = v.x;
        Qs[(k0 + 1) * FL_STR + r] = v.y;
        Qs[(k0 + 2) * FL_STR + r] = v.z;
        Qs[(k0 + 3) * FL_STR + r] = v.w;
    }

    float Oa[4][4];
    float m_i[4], l_i[4];
#pragma unroll
    for (int i = 0; i < 4; i++) {
        m_i[i] = -1e30f;
        l_i[i] = 0.0f;
#pragma unroll
        for (int j = 0; j < 4; j++) Oa[i][j] = 0.0f;
    }

    const int rg0 = qt * 64 + ty * 4;

    for (int j = 0; j <= qt; ++j) {
        __syncthreads();   // prev iter's readers of Ks/Vs/Ps done; Qs loaded
        // Load K (transposed) and V (direct) tiles
        for (int i = tid; i < 64 * 16; i += 256) {
            const int r  = i >> 4;
            const int k0 = (i & 15) << 2;
            const float4 kv = *(const float4*)(Kg + (size_t)(j * 64 + r) * DMODEL + k0);
            Ks[(k0 + 0) * FL_STR + r] = kv.x;
            Ks[(k0 + 1) * FL_STR + r] = kv.y;
            Ks[(k0 + 2) * FL_STR + r] = kv.z;
            Ks[(k0 + 3) * FL_STR + r] = kv.w;
            const float4 vv = *(const float4*)(Vg + (size_t)(j * 64 + r) * DMODEL + k0);
            *(float4*)&Vs[r * FL_STR + k0] = vv;
        }
        __syncthreads();

        // S = Q K^T  (4x4 per thread)
        float S[4][4];
#pragma unroll
        for (int i = 0; i < 4; i++)
#pragma unroll
            for (int jj = 0; jj < 4; jj++) S[i][jj] = 0.0f;

#pragma unroll 8
        for (int kk = 0; kk < 64; kk++) {
            const float4 av = *(const float4*)&Qs[kk * FL_STR + ty * 4];
            const float4 bv = *(const float4*)&Ks[kk * FL_STR + tx * 4];
            const float a[4] = {av.x, av.y, av.z, av.w};
            const float bb[4] = {bv.x, bv.y, bv.z, bv.w};
#pragma unroll
            for (int i = 0; i < 4; i++)
#pragma unroll
                for (int jj = 0; jj < 4; jj++) S[i][jj] += a[i] * bb[jj];
        }

        const float scl = 0.125f;   // 1/sqrt(64)
        if (j == qt) {
#pragma unroll
            for (int i = 0; i < 4; i++)
#pragma unroll
                for (int jj = 0; jj < 4; jj++) {
                    const int cg = j * 64 + tx * 4 + jj;
                    S[i][jj] = (cg <= rg0 + i) ? S[i][jj] * scl : -1e30f;
                }
        } else {
#pragma unroll
            for (int i = 0; i < 4; i++)
#pragma unroll
                for (int jj = 0; jj < 4; jj++) S[i][jj] *= scl;
        }

        // Online softmax per row (reduce across the 16 tx lanes)
        float P[4][4];
#pragma unroll
        for (int i = 0; i < 4; i++) {
            float rm = fmaxf(fmaxf(S[i][0], S[i][1]), fmaxf(S[i][2], S[i][3]));
#pragma unroll
            for (int d = 1; d < 16; d <<= 1)
                rm = fmaxf(rm, __shfl_xor_sync(0xffffffffu, rm, d));
            const float mnew = fmaxf(m_i[i], rm);
            const float corr = __expf(m_i[i] - mnew);
            float rs = 0.0f;
#pragma unroll
            for (int jj = 0; jj < 4; jj++) {
                const float p = __expf(S[i][jj] - mnew);
                P[i][jj] = p;
                rs += p;
            }
#pragma unroll
            for (int d = 1; d < 16; d <<= 1)
                rs += __shfl_xor_sync(0xffffffffu, rs, d);
            l_i[i] = l_i[i] * corr + rs;
            m_i[i] = mnew;
#pragma unroll
            for (int jj = 0; jj < 4; jj++) Oa[i][jj] *= corr;
        }

        // Stage P to smem (row-major)
#pragma unroll
        for (int i = 0; i < 4; i++)
            *(float4*)&Ps[(ty * 4 + i) * FL_STR + tx * 4] =
                make_float4(P[i][0], P[i][1], P[i][2], P[i][3]);
        __syncthreads();

        // O += P @ V
#pragma unroll 4
        for (int c0 = 0; c0 < 64; c0 += 4) {
            const float4 v0 = *(const float4*)&Vs[(c0 + 0) * FL_STR + tx * 4];
            const float4 v1 = *(const float4*)&Vs[(c0 + 1) * FL_STR + tx * 4];
            const float4 v2 = *(const float4*)&Vs[(c0 + 2) * FL_STR + tx * 4];
            const float4 v3 = *(const float4*)&Vs[(c0 + 3) * FL_STR + tx * 4];
#pragma unroll
            for (int i = 0; i < 4; i++) {
                const float4 pv = *(const float4*)&Ps[(ty * 4 + i) * FL_STR + c0];
                Oa[i][0] += pv.x * v0.x + pv.y * v1.x + pv.z * v2.x + pv.w * v3.x;
                Oa[i][1] += pv.x * v0.y + pv.y * v1.y + pv.z * v2.y + pv.w * v3.y;
                Oa[i][2] += pv.x * v0.z + pv.y * v1.z + pv.z * v2.z + pv.w * v3.z;
                Oa[i][3] += pv.x * v0.w + pv.y * v1.w + pv.z * v2.w + pv.w * v3.w;
            }
        }
    }

    // Normalize and write [B,T,heads*HDIM] (head-major within D: matches ref)
#pragma unroll
    for (int i = 0; i < 4; i++) {
        const float inv = 1.0f / l_i[i];
        const float4 o = make_float4(Oa[i][0] * inv, Oa[i][1] * inv,
                                     Oa[i][2] * inv, Oa[i][3] * inv);
        *(float4*)(Og + (size_t)(qt * 64 + ty * 4 + i) * DMODEL + tx * 4) = o;
    }
}

// ---------------------------------------------------------------------------
extern "C" void kernel_launch(void* const* d_in, const int* in_sizes, int n_in,
                              void* d_out, int out_size)
{
    const float* x  = (const float*)d_in[0];
    const float* Wk = (const float*)d_in[1];
    const float* Wq = (const float*)d_in[2];
    const float* Wv = (const float*)d_in[3];
    const float* Wo = (const float*)d_in[4];
    float* out = (float*)d_out;
    (void)in_sizes; (void)n_in; (void)out_size;

    const int flash_smem = FL_SMEM_FLOATS * (int)sizeof(float);  // 69632 B
    cudaFuncSetAttribute(flash_attn,
                         cudaFuncAttributeMaxDynamicSharedMemorySize, flash_smem);

    // 1) QKV projections: g_k/g_q/g_v = x @ W{k,q,v}^T
    gemm_nt<true><<<dim3(M_TOK / 128, DMODEL / 128, 3), 256>>>(x, Wk, Wq, Wv, nullptr);

    // 2) Causal flash attention per (q-tile, b*h)
    flash_attn<<<dim3(TSEQ / 64, 8 * NHEADS), 256, flash_smem>>>();

    // 3) Output projection: out = g_ao @ Wo^T
    gemm_nt<false><<<dim3(M_TOK / 128, DMODEL / 128, 1), 256>>>(nullptr, Wo, nullptr, nullptr, out);
}

// round 3
// speedup vs baseline: 2.9382x; 2.9382x over previous
#include <cuda_runtime.h>

#define M_TOK  8192
#define DMODEL 1024
#define TSEQ   1024
#define NHEADS 16
#define HDIM   64

// Scratch (device globals: allocation-free rule)
__device__ float g_q [M_TOK * DMODEL];
__device__ float g_k [M_TOK * DMODEL];
__device__ float g_v [M_TOK * DMODEL];
__device__ float g_ao[M_TOK * DMODEL];

// f32 -> tf32 with round-to-nearest (halves error vs truncation)
__device__ __forceinline__ unsigned f2tf(float f) {
    unsigned r;
    asm("cvt.rna.tf32.f32 %0, %1;" : "=r"(r) : "f"(f));
    return r;
}

// m16n8k8 row.col tf32 mma, f32 accumulate
__device__ __forceinline__ void mma_tf32(float* c, const unsigned* a, const unsigned* b) {
    asm volatile(
        "mma.sync.aligned.m16n8k8.row.col.f32.tf32.tf32.f32 "
        "{%0,%1,%2,%3}, {%4,%5,%6,%7}, {%8,%9}, {%0,%1,%2,%3};"
        : "+f"(c[0]), "+f"(c[1]), "+f"(c[2]), "+f"(c[3])
        : "r"(a[0]), "r"(a[1]), "r"(a[2]), "r"(a[3]), "r"(b[0]), "r"(b[1]));
}

// ---------------------------------------------------------------------------
// GEMM C = A @ W^T. A:[M,1024] rm, W:[1024,1024] rm (both K-contiguous).
// 128x128 block tile, Ktile=32, 256 thr = 8 warps (2m x 4n), warp = 64x32.
// Double-buffered via register prefetch. TF32 tensor cores.
// ---------------------------------------------------------------------------
#define GSTR 36   // smem row stride (words) for [128][32] tiles

template <bool QKV>
__global__ __launch_bounds__(256, 1)
void gemm_tc(const float* __restrict__ A,
             const float* __restrict__ W0,
             const float* __restrict__ W1,
             const float* __restrict__ W2,
             float* __restrict__ Cout)
{
    const float* W;
    float* C;
    if (QKV) {
        const int z = blockIdx.z;
        W = (z == 0) ? W0 : (z == 1) ? W1 : W2;
        C = (z == 0) ? g_k : (z == 1) ? g_q : g_v;
    } else {
        W = W0;
        C = Cout;
    }
    const float* Asrc = QKV ? A : (const float*)g_ao;

    __shared__ unsigned As[128 * GSTR];
    __shared__ unsigned Bs[128 * GSTR];

    const int tid  = threadIdx.x;
    const int warp = tid >> 5;
    const int lane = tid & 31;
    const int g    = lane >> 2;        // group id 0..7
    const int t    = lane & 3;         // thread-in-group 0..3
    const int wm   = (warp >> 2) * 64; // warp m offset in block tile
    const int wn   = (warp & 3) * 32;  // warp n offset

    const int m0 = blockIdx.x * 128;
    const int n0 = blockIdx.y * 128;

    // global load mapping: per chunk i (0..3): row = (tid>>3)+32*i, col4 = (tid&7)*4
    const int lr = tid >> 3;
    const int lc = (tid & 7) * 4;
    const float* Ap = Asrc + (size_t)(m0 + lr) * DMODEL + lc;
    const float* Wp = W    + (size_t)(n0 + lr) * DMODEL + lc;
    const int sbase = lr * GSTR + lc;

    float acc[4][4][4];
#pragma unroll
    for (int mt = 0; mt < 4; mt++)
#pragma unroll
        for (int nt = 0; nt < 4; nt++)
#pragma unroll
            for (int q = 0; q < 4; q++) acc[mt][nt][q] = 0.0f;

    float4 ra[4], rb[4];
#pragma unroll
    for (int i = 0; i < 4; i++) {
        ra[i] = *(const float4*)(Ap + (size_t)(32 * i) * DMODEL);
        rb[i] = *(const float4*)(Wp + (size_t)(32 * i) * DMODEL);
    }

    for (int kt = 0; kt < 32; kt++) {
        __syncthreads();   // previous compute done before overwrite
#pragma unroll
        for (int i = 0; i < 4; i++) {
            *(uint4*)&As[sbase + 32 * i * GSTR] =
                make_uint4(f2tf(ra[i].x), f2tf(ra[i].y), f2tf(ra[i].z), f2tf(ra[i].w));
            *(uint4*)&Bs[sbase + 32 * i * GSTR] =
                make_uint4(f2tf(rb[i].x), f2tf(rb[i].y), f2tf(rb[i].z), f2tf(rb[i].w));
        }
        __syncthreads();

        if (kt < 31) {
            const size_t ko = (size_t)(kt + 1) * 32;
#pragma unroll
            for (int i = 0; i < 4; i++) {
                ra[i] = *(const float4*)(Ap + (size_t)(32 * i) * DMODEL + ko);
                rb[i] = *(const float4*)(Wp + (size_t)(32 * i) * DMODEL + ko);
            }
        }

#pragma unroll
        for (int ks = 0; ks < 4; ks++) {
            unsigned af[4][4];
#pragma unroll
            for (int mt = 0; mt < 4; mt++) {
                const int ab = (wm + mt * 16 + g) * GSTR + ks * 8 + t;
                af[mt][0] = As[ab];
                af[mt][1] = As[ab + 8 * GSTR];
                af[mt][2] = As[ab + 4];
                af[mt][3] = As[ab + 8 * GSTR + 4];
            }
            unsigned bf[4][2];
#pragma unroll
            for (int nt = 0; nt < 4; nt++) {
                const int bb = (wn + nt * 8 + g) * GSTR + ks * 8 + t;
                bf[nt][0] = Bs[bb];
                bf[nt][1] = Bs[bb + 4];
            }
#pragma unroll
            for (int mt = 0; mt < 4; mt++)
#pragma unroll
                for (int nt = 0; nt < 4; nt++)
                    mma_tf32(acc[mt][nt], af[mt], bf[nt]);
        }
    }

    // epilogue: c0/c1 -> (row, 2t..2t+1), c2/c3 -> (row+8, ...)
#pragma unroll
    for (int mt = 0; mt < 4; mt++) {
#pragma unroll
        for (int nt = 0; nt < 4; nt++) {
            const int row = m0 + wm + mt * 16 + g;
            const int col = n0 + wn + nt * 8 + 2 * t;
            *(float2*)&C[(size_t)row * DMODEL + col] =
                make_float2(acc[mt][nt][0], acc[mt][nt][1]);
            *(float2*)&C[(size_t)(row + 8) * DMODEL + col] =
                make_float2(acc[mt][nt][2], acc[mt][nt][3]);
        }
    }
}

// ---------------------------------------------------------------------------
// Flash attention, TF32 tensor cores. Block = 64 q-rows x one (b,h).
// 128 threads = 4 warps, warp owns 16 rows (one m16 tile), full n=64.
// All tiles row-major [token][dim] in smem; PV uses V^T[n][k] = Vs[k][n].
// ---------------------------------------------------------------------------
#define FSTR 68
#define FL_SMEM_WORDS (4 * 64 * FSTR)

__global__ __launch_bounds__(128, 1)
void flash_tc()
{
    extern __shared__ unsigned sm[];
    unsigned* Qs = sm;                 // [64][FSTR] tf32, pre-scaled by 1/8
    unsigned* Ks = sm + 64 * FSTR;     // [64][FSTR]
    unsigned* Vs = sm + 2 * 64 * FSTR; // [64][FSTR]
    unsigned* Ps = sm + 3 * 64 * FSTR; // [64][FSTR]

    const int qt = blockIdx.x;          // 0..15
    const int b  = blockIdx.y >> 4;
    const int h  = blockIdx.y & 15;
    const size_t base = (size_t)b * TSEQ * DMODEL + (size_t)h * HDIM;
    const float* Qg = g_q + base;
    const float* Kg = g_k + base;
    const float* Vg = g_v + base;
    float*       Og = g_ao + base;

    const int tid  = threadIdx.x;
    const int warp = tid >> 5;
    const int lane = tid & 31;
    const int g    = lane >> 2;
    const int t    = lane & 3;
    const int wrow = warp * 16;

    // Load Q (64x64), scaled by 1/8 so S comes out pre-scaled
    const int lr = tid >> 4;       // 0..7
    const int lc = (tid & 15) * 4; // 0..60
#pragma unroll
    for (int i = 0; i < 8; i++) {
        const int row = lr + 8 * i;
        float4 v = *(const float4*)(Qg + (size_t)(qt * 64 + row) * DMODEL + lc);
        *(uint4*)&Qs[row * FSTR + lc] =
            make_uint4(f2tf(v.x * 0.125f), f2tf(v.y * 0.125f),
                       f2tf(v.z * 0.125f), f2tf(v.w * 0.125f));
    }

    float o[8][4];
    float m_i[2], l_i[2];
#pragma unroll
    for (int nt = 0; nt < 8; nt++)
#pragma unroll
        for (int q = 0; q < 4; q++) o[nt][q] = 0.0f;
    m_i[0] = m_i[1] = -1e30f;
    l_i[0] = l_i[1] = 0.0f;

    for (int j = 0; j <= qt; ++j) {
        __syncthreads();   // all warps done with previous K/V tiles (and Q loaded)
#pragma unroll
        for (int i = 0; i < 8; i++) {
            const int row = lr + 8 * i;
            float4 kv = *(const float4*)(Kg + (size_t)(j * 64 + row) * DMODEL + lc);
            *(uint4*)&Ks[row * FSTR + lc] =
                make_uint4(f2tf(kv.x), f2tf(kv.y), f2tf(kv.z), f2tf(kv.w));
            float4 vv = *(const float4*)(Vg + (size_t)(j * 64 + row) * DMODEL + lc);
            *(uint4*)&Vs[row * FSTR + lc] =
                make_uint4(f2tf(vv.x), f2tf(vv.y), f2tf(vv.z), f2tf(vv.w));
        }
        __syncthreads();

        // S = (Q*scl) K^T : warp computes rows [wrow, wrow+16), all 64 cols
        float s[8][4];
#pragma unroll
        for (int nt = 0; nt < 8; nt++)
#pragma unroll
            for (int q = 0; q < 4; q++) s[nt][q] = 0.0f;

#pragma unroll
        for (int ks = 0; ks < 8; ks++) {
            unsigned a[4];
            const int ab = (wrow + g) * FSTR + ks * 8 + t;
            a[0] = Qs[ab];
            a[1] = Qs[ab + 8 * FSTR];
            a[2] = Qs[ab + 4];
            a[3] = Qs[ab + 8 * FSTR + 4];
#pragma unroll
            for (int nt = 0; nt < 8; nt++) {
                unsigned bq[2];
                const int bb = (nt * 8 + g) * FSTR + ks * 8 + t;
                bq[0] = Ks[bb];
                bq[1] = Ks[bb + 4];
                mma_tf32(s[nt], a, bq);
            }
        }

        // causal mask on the diagonal tile
        const int rg0 = qt * 64 + wrow + g;   // row for c0/c1; +8 for c2/c3
        if (j == qt) {
#pragma unroll
            for (int nt = 0; nt < 8; nt++) {
                const int col = j * 64 + nt * 8 + 2 * t;
                if (col     > rg0)     s[nt][0] = -1e30f;
                if (col + 1 > rg0)     s[nt][1] = -1e30f;
                if (col     > rg0 + 8) s[nt][2] = -1e30f;
                if (col + 1 > rg0 + 8) s[nt][3] = -1e30f;
            }
        }

        // online softmax: row0 = g (c0,c1), row1 = g+8 (c2,c3)
#pragma unroll
        for (int r = 0; r < 2; r++) {
            float rm = -1e30f;
#pragma unroll
            for (int nt = 0; nt < 8; nt++)
                rm = fmaxf(rm, fmaxf(s[nt][2 * r], s[nt][2 * r + 1]));
            rm = fmaxf(rm, __shfl_xor_sync(0xffffffffu, rm, 1));
            rm = fmaxf(rm, __shfl_xor_sync(0xffffffffu, rm, 2));
            const float mnew = fmaxf(m_i[r], rm);
            const float corr = __expf(m_i[r] - mnew);
            float rs = 0.0f;
#pragma unroll
            for (int nt = 0; nt < 8; nt++) {
                const float p0 = __expf(s[nt][2 * r]     - mnew);
                const float p1 = __expf(s[nt][2 * r + 1] - mnew);
                s[nt][2 * r]     = p0;
                s[nt][2 * r + 1] = p1;
                rs += p0 + p1;
            }
            rs += __shfl_xor_sync(0xffffffffu, rs, 1);
            rs += __shfl_xor_sync(0xffffffffu, rs, 2);
            l_i[r] = l_i[r] * corr + rs;
            m_i[r] = mnew;
#pragma unroll
            for (int nt = 0; nt < 8; nt++) {
                o[nt][2 * r]     *= corr;
                o[nt][2 * r + 1] *= corr;
            }
        }

        // stage P (tf32) into Ps — warp-private rows, no block sync needed
#pragma unroll
        for (int nt = 0; nt < 8; nt++) {
            *(uint2*)&Ps[(wrow + g) * FSTR + nt * 8 + 2 * t] =
                make_uint2(f2tf(s[nt][0]), f2tf(s[nt][1]));
            *(uint2*)&Ps[(wrow + g + 8) * FSTR + nt * 8 + 2 * t] =
                make_uint2(f2tf(s[nt][2]), f2tf(s[nt][3]));
        }
        __syncwarp();

        // O += P @ V   (B[n=dim][k=token] = Vs[token][dim])
#pragma unroll
        for (int ks = 0; ks < 8; ks++) {
            unsigned a[4];
            const int ab = (wrow + g) * FSTR + ks * 8 + t;
            a[0] = Ps[ab];
            a[1] = Ps[ab + 8 * FSTR];
            a[2] = Ps[ab + 4];
            a[3] = Ps[ab + 8 * FSTR + 4];
#pragma unroll
            for (int nt = 0; nt < 8; nt++) {
                unsigned bq[2];
                bq[0] = Vs[(ks * 8 + t)     * FSTR + nt * 8 + g];
                bq[1] = Vs[(ks * 8 + t + 4) * FSTR + nt * 8 + g];
                mma_tf32(o[nt], a, bq);
            }
        }
        __syncwarp();   // Ps reads done before next-iter overwrite by this warp
    }

    // normalize and write out (head-major layout matches reference reshape)
    const float inv0 = 1.0f / l_i[0];
    const float inv1 = 1.0f / l_i[1];
#pragma unroll
    for (int nt = 0; nt < 8; nt++) {
        const int row = qt * 64 + wrow + g;
        const int col = nt * 8 + 2 * t;
        *(float2*)(Og + (size_t)row * DMODEL + col) =
            make_float2(o[nt][0] * inv0, o[nt][1] * inv0);
        *(float2*)(Og + (size_t)(row + 8) * DMODEL + col) =
            make_float2(o[nt][2] * inv1, o[nt][3] * inv1);
    }
}

// ---------------------------------------------------------------------------
extern "C" void kernel_launch(void* const* d_in, const int* in_sizes, int n_in,
                              void* d_out, int out_size)
{
    const float* x  = (const float*)d_in[0];
    const float* Wk = (const float*)d_in[1];
    const float* Wq = (const float*)d_in[2];
    const float* Wv = (const float*)d_in[3];
    const float* Wo = (const float*)d_in[4];
    float* out = (float*)d_out;
    (void)in_sizes; (void)n_in; (void)out_size;

    const int flash_smem = FL_SMEM_WORDS * (int)sizeof(unsigned);  // 69632 B
    cudaFuncSetAttribute(flash_tc,
                         cudaFuncAttributeMaxDynamicSharedMemorySize, flash_smem);

    // 1) QKV projections (tensor cores, tf32)
    gemm_tc<true><<<dim3(M_TOK / 128, DMODEL / 128, 3), 256>>>(x, Wk, Wq, Wv, nullptr);

    // 2) causal flash attention (tensor cores, tf32)
    flash_tc<<<dim3(TSEQ / 64, 8 * NHEADS), 128, flash_smem>>>();

    // 3) output projection
    gemm_tc<false><<<dim3(M_TOK / 128, DMODEL / 128, 1), 256>>>(nullptr, Wo, nullptr, nullptr, out);
}